// round 7
// baseline (speedup 1.0000x reference)
#include <cuda_runtime.h>
#include <cstdint>

// Problem dims
#define BDIM 1024
#define TDIM 512
#define IDIM 64
#define HDIM 256
#define KDIM 320            // I + H
#define KC   32             // K-chunk
#define NCHUNK 10           // KDIM / KC (chunks 0..1 = x, 2..9 = h)

// Partitioning
#define NBX 16              // batch groups (independent barrier domains)
#define NUY 8               // unit blocks per group
#define GRID_CTAS (NBX*NUY) // 128 <= 148 SMs -> co-resident, persistent-safe
#define BM 64               // batch rows per CTA
#define UN 32               // hidden units per CTA (x4 gates = 128 gate rows)
#define NTHREADS 256
#define ZS 68               // z smem row stride in floats (16B-aligned rows)

#define SMEM_FLOATS (KDIM*128 + 2*KC*ZS + 128)
#define SMEM_BYTES  (SMEM_FLOATS*4)   // 181,760 B < 227KB max dyn smem

// Persistent global state (no allocations allowed by harness rules).
// Per-batch-group barriers: only the 8 CTAs sharing a batch block exchange
// h data, so each group synchronizes independently (fan-in 8).
__device__ float g_hbuf[2][BDIM*HDIM];
__device__ unsigned int g_bar_count[NBX];   // zero-init
__device__ unsigned int g_bar_gen[NBX];     // zero-init

// ---- packed f32x2 helpers (Blackwell FFMA2: 2x FLOP per fma-pipe issue) ----
__device__ __forceinline__ void fma2(unsigned long long& d, unsigned long long a, unsigned long long b) {
    asm("fma.rn.f32x2 %0, %1, %2, %0;" : "+l"(d) : "l"(a), "l"(b));
}
__device__ __forceinline__ unsigned long long dup2(float x) {
    unsigned long long r;
    asm("mov.b64 %0, {%1, %1};" : "=l"(r) : "f"(x));
    return r;
}
__device__ __forceinline__ void unpack2(unsigned long long v, float& lo, float& hi) {
    asm("mov.b64 {%0, %1}, %2;" : "=f"(lo), "=f"(hi) : "l"(v));
}

__device__ __forceinline__ float sigmoidf_(float x) {
    return 1.0f / (1.0f + __expf(-x));
}
__device__ __forceinline__ float tanhf_(float x) {
    float e = __expf(-2.0f * fabsf(x));
    float t = (1.0f - e) / (1.0f + e);
    return copysignf(t, x);
}

__global__ void __launch_bounds__(NTHREADS, 1)
lstm_persistent_kernel(const float* __restrict__ x,      // [B,T,I]
                       const float* __restrict__ W_ih,   // [4H,I]
                       const float* __restrict__ W_hh,   // [4H,H]
                       const float* __restrict__ b_ih,   // [4H]
                       const float* __restrict__ b_hh,   // [4H]
                       const float* __restrict__ W_out,  // [1,H]
                       const float* __restrict__ b_out,  // [1]
                       float* __restrict__ out)          // [B,1]
{
    extern __shared__ float smem[];
    float* Wsh  = smem;                  // [KDIM][128]  Wsh[k][j*4+q]
    float* zsh0 = Wsh + KDIM*128;        // [KC][ZS] ping
    float* zsh1 = zsh0 + KC*ZS;          // [KC][ZS] pong
    float* bsh  = zsh1 + KC*ZS;          // [128]    b_ih+b_hh, ordered [j*4+q]

    const int bid = blockIdx.x;
    const int bx  = bid & (NBX - 1);   // batch group
    const int uy  = bid >> 4;          // unit block within group
    const int tid = threadIdx.x;
    const int tb  = tid >> 5;          // warp id -> 8 batch rows
    const int tr  = tid & 31;          // lane    -> local hidden unit

    volatile unsigned int* genp   = &g_bar_gen[bx];
    unsigned int*          countp = &g_bar_count[bx];
    unsigned int gen_obs = 0;          // only meaningful on tid==0

    // staging thread mapping (fixed per thread)
    const int sb0 = tid >> 3;            // local batch row, pass 0
    const int sb1 = (tid + NTHREADS) >> 3;
    const int skg = (tid & 7) * 4;       // k offset within chunk: 0,4,...,28

    // ---- one-time: W slice -> SMEM (gate rows interleaved [unit][gate]) ----
    for (int idx = tid; idx < KDIM * 128; idx += NTHREADS) {
        int k   = idx >> 7;
        int col = idx & 127;
        int j   = col >> 2;
        int q   = col & 3;
        int row = q * HDIM + uy * UN + j;
        Wsh[idx] = (k < IDIM) ? W_ih[row * IDIM + k]
                              : W_hh[row * HDIM + (k - IDIM)];
    }
    if (tid < 128) {
        int j = tid >> 2, q = tid & 3;
        int row = q * HDIM + uy * UN + j;
        bsh[tid] = b_ih[row] + b_hh[row];
    }

    // ---- zero owned h0 slice (buffer 0 is read at t=0) ----
    for (int i = tid; i < BM * UN; i += NTHREADS) {
        int b = i >> 5;
        int j = i & 31;
        __stcg(&g_hbuf[0][(bx * BM + b) * HDIM + uy * UN + j], 0.0f);
    }

    float c[8];
#pragma unroll
    for (int m = 0; m < 8; ++m) c[m] = 0.0f;

    // ---- split group barrier: ARRIVE now; WAIT overlapped into step 0 ----
    __syncthreads();
    __threadfence();
    if (tid == 0) {
        gen_obs = *genp;
        if (atomicAdd(countp, 1u) == NUY - 1) {
            *countp = 0;
            __threadfence();
            atomicAdd(&g_bar_gen[bx], 1u);
        }
    }

    float4 bias4 = *reinterpret_cast<const float4*>(&bsh[tr * 4]);

    // stage an x chunk (ci in {0,1}) of timestep tt into zbuf
    auto stage_x = [&](int ci, float* zbuf, int tt) {
        const int k0 = ci * KC;
#pragma unroll
        for (int it = 0; it < 2; ++it) {
            int b  = it ? sb1 : sb0;
            float4 v = __ldg(reinterpret_cast<const float4*>(
                &x[((bx * BM + b) * TDIM + tt) * IDIM + k0 + skg]));
            zbuf[(skg + 0) * ZS + b] = v.x;
            zbuf[(skg + 1) * ZS + b] = v.y;
            zbuf[(skg + 2) * ZS + b] = v.z;
            zbuf[(skg + 3) * ZS + b] = v.w;
        }
    };

    // prologue: chunk 0 of t=0
    stage_x(0, zsh0, 0);
    __syncthreads();

#pragma unroll 1
    for (int t = 0; t < TDIM; ++t) {
        const float* hr = g_hbuf[t & 1];
        float*       hw = g_hbuf[(t + 1) & 1];

        // stage an h chunk (ci in 2..9) into zbuf
        auto stage_h = [&](int ci, float* zbuf) {
            const int k0 = ci * KC - IDIM;
#pragma unroll
            for (int it = 0; it < 2; ++it) {
                int b  = it ? sb1 : sb0;
                float4 v = __ldcg(reinterpret_cast<const float4*>(
                    &hr[(bx * BM + b) * HDIM + k0 + skg]));
                zbuf[(skg + 0) * ZS + b] = v.x;
                zbuf[(skg + 1) * ZS + b] = v.y;
                zbuf[(skg + 2) * ZS + b] = v.z;
                zbuf[(skg + 3) * ZS + b] = v.w;
            }
        };

        unsigned long long acc2[4][4];   // [gate q][batch pair p]
#pragma unroll
        for (int q = 0; q < 4; ++q)
#pragma unroll
            for (int p = 0; p < 4; ++p) acc2[q][p] = 0ull;

        // rank-KC FMA2 update from staged zbuf
        auto compute = [&](int ci, const float* zbuf) {
            const int k0 = ci * KC;
#pragma unroll 4
            for (int kk = 0; kk < KC; ++kk) {
                float4 w4 = *reinterpret_cast<const float4*>(
                    &Wsh[(k0 + kk) * 128 + tr * 4]);
                unsigned long long w2[4];
                w2[0] = dup2(w4.x); w2[1] = dup2(w4.y);
                w2[2] = dup2(w4.z); w2[3] = dup2(w4.w);
                ulonglong2 za = *reinterpret_cast<const ulonglong2*>(
                    &zbuf[kk * ZS + tb * 8]);          // batch pairs (0,1),(2,3)
                ulonglong2 zb = *reinterpret_cast<const ulonglong2*>(
                    &zbuf[kk * ZS + tb * 8 + 4]);      // batch pairs (4,5),(6,7)
                unsigned long long z2[4] = { za.x, za.y, zb.x, zb.y };
#pragma unroll
                for (int q = 0; q < 4; ++q) {
#pragma unroll
                    for (int p = 0; p < 4; ++p) fma2(acc2[q][p], w2[q], z2[p]);
                }
            }
        };

        // --- pipelined chunk schedule (one sync per chunk, LDG hidden) ---
        stage_x(1, zsh1, t);              // load chunk 1 while computing 0
        compute(0, zsh0);
        __syncthreads();

        // WAIT: previous step's h stores from this group visible (overlapped
        // with the x-chunk compute above).
        if (tid == 0) {
            while (*genp == gen_obs) { }
            __threadfence();   // acquire-side ordering before h reads
        }
        __syncthreads();

        stage_h(2, zsh0);                 // first h chunk
        compute(1, zsh1);
        __syncthreads();

#pragma unroll 1
        for (int ci = 2; ci < NCHUNK - 1; ++ci) {
            if ((ci + 1) & 1) stage_h(ci + 1, zsh1);
            else              stage_h(ci + 1, zsh0);
            if (ci & 1) compute(ci, zsh1);
            else        compute(ci, zsh0);
            __syncthreads();
        }

        // prefetch chunk 0 of next step (x-only) under the last compute+epilogue
        if (t + 1 < TDIM) stage_x(0, zsh0, t + 1);
        compute(NCHUNK - 1, zsh1);        // chunk 9 lives in pong buffer

        // ---- epilogue: gates -> (c,h); c stays in registers ----
#pragma unroll
        for (int p = 0; p < 4; ++p) {
            float gi0, gi1, gf0, gf1, gg0, gg1, go0, go1;
            unpack2(acc2[0][p], gi0, gi1);
            unpack2(acc2[1][p], gf0, gf1);
            unpack2(acc2[2][p], gg0, gg1);
            unpack2(acc2[3][p], go0, go1);
#pragma unroll
            for (int h2 = 0; h2 < 2; ++h2) {
                int m = p * 2 + h2;
                float gi = (h2 ? gi1 : gi0) + bias4.x;
                float gf = (h2 ? gf1 : gf0) + bias4.y;
                float gg = (h2 ? gg1 : gg0) + bias4.z;
                float go = (h2 ? go1 : go0) + bias4.w;
                float iv = sigmoidf_(gi);
                float fv = sigmoidf_(gf);
                float gv = tanhf_(gg);
                float ov = sigmoidf_(go);
                float cn = fv * c[m] + iv * gv;
                c[m] = cn;
                float hn = ov * tanhf_(cn);
                __stcg(&hw[(bx * BM + tb * 8 + m) * HDIM + uy * UN + tr], hn);
            }
        }

        // ---- ARRIVE for this step (wait is overlapped into next step).
        // The __syncthreads also orders this step's zsh0 prefetch stores
        // before next step's compute(0) reads. ----
        __syncthreads();
        __threadfence();
        if (tid == 0) {
            gen_obs = *genp;
            if (atomicAdd(countp, 1u) == NUY - 1) {
                *countp = 0;
                __threadfence();
                atomicAdd(&g_bar_gen[bx], 1u);
            }
        }
    }

    // ---- final wait: group's last h stores visible before the head GEMV ----
    if (tid == 0) {
        while (*genp == gen_obs) { }
        __threadfence();
    }
    __syncthreads();

    // ---- output head: out[b] = h_last . W_out + b_out (vectorized) ----
    if (uy == 0 && tid < BM) {
        const float* hl = g_hbuf[TDIM & 1];   // buffer written at t = T-1
        int b = bx * BM + tid;
        float sum = 0.0f;
#pragma unroll 8
        for (int j = 0; j < HDIM; j += 4) {
            float4 hv = *reinterpret_cast<const float4*>(&hl[b * HDIM + j]);
            float4 wv = __ldg(reinterpret_cast<const float4*>(&W_out[j]));
            sum += hv.x * wv.x + hv.y * wv.y + hv.z * wv.z + hv.w * wv.w;
        }
        out[b] = sum + __ldg(&b_out[0]);
    }
}

extern "C" void kernel_launch(void* const* d_in, const int* in_sizes, int n_in,
                              void* d_out, int out_size) {
    const float* input_seq = (const float*)d_in[0];
    const float* W_ih      = (const float*)d_in[1];
    const float* W_hh      = (const float*)d_in[2];
    const float* b_ih      = (const float*)d_in[3];
    const float* b_hh      = (const float*)d_in[4];
    const float* W_out     = (const float*)d_in[5];
    const float* b_out     = (const float*)d_in[6];
    float* out             = (float*)d_out;

    cudaFuncSetAttribute(lstm_persistent_kernel,
                         cudaFuncAttributeMaxDynamicSharedMemorySize, SMEM_BYTES);
    lstm_persistent_kernel<<<GRID_CTAS, NTHREADS, SMEM_BYTES>>>(
        input_seq, W_ih, W_hh, b_ih, b_hh, W_out, b_out, out);
}

// round 10
// speedup vs baseline: 1.0240x; 1.0240x over previous
#include <cuda_runtime.h>
#include <cstdint>

// Problem dims
#define BDIM 1024
#define TDIM 512
#define IDIM 64
#define HDIM 256
#define KDIM 320            // I + H
#define KC   32             // K-chunk
#define NCHUNK 10           // KDIM / KC (chunks 0..1 = x, 2..9 = h)

// Partitioning
#define NBX 16              // batch groups (independent barrier domains)
#define NUY 8               // unit blocks per group
#define GRID_CTAS (NBX*NUY) // 128 <= 148 SMs -> co-resident, persistent-safe
#define BM 64               // batch rows per CTA
#define UN 32               // hidden units per CTA (x4 gates = 128 gate rows)
#define NTHREADS 512        // 16 warps -> 4 warps/SMSP for latency hiding
#define ZS 68               // z smem row stride in floats (16B-aligned rows)

#define SMEM_FLOATS (KDIM*128 + 2*KC*ZS + 128)
#define SMEM_BYTES  (SMEM_FLOATS*4)   // 181,760 B < 227KB max dyn smem

// Persistent global state (no allocations allowed by harness rules).
__device__ float g_hbuf[2][BDIM*HDIM];
__device__ unsigned int g_bar_count[NBX];   // zero-init
__device__ unsigned int g_bar_gen[NBX];     // zero-init

// ---- packed f32x2 helpers (Blackwell FFMA2: 2x FLOP per fma-pipe issue) ----
__device__ __forceinline__ void fma2(unsigned long long& d, unsigned long long a, unsigned long long b) {
    asm("fma.rn.f32x2 %0, %1, %2, %0;" : "+l"(d) : "l"(a), "l"(b));
}
__device__ __forceinline__ unsigned long long dup2(float x) {
    unsigned long long r;
    asm("mov.b64 %0, {%1, %1};" : "=l"(r) : "f"(x));
    return r;
}
__device__ __forceinline__ void unpack2(unsigned long long v, float& lo, float& hi) {
    asm("mov.b64 {%0, %1}, %2;" : "=f"(lo), "=f"(hi) : "l"(v));
}

__device__ __forceinline__ float sigmoidf_(float x) {
    return 1.0f / (1.0f + __expf(-x));
}
__device__ __forceinline__ float tanhf_(float x) {
    float e = __expf(-2.0f * fabsf(x));
    float t = (1.0f - e) / (1.0f + e);
    return copysignf(t, x);
}

__global__ void __launch_bounds__(NTHREADS, 1)
lstm_persistent_kernel(const float* __restrict__ x,      // [B,T,I]
                       const float* __restrict__ W_ih,   // [4H,I]
                       const float* __restrict__ W_hh,   // [4H,H]
                       const float* __restrict__ b_ih,   // [4H]
                       const float* __restrict__ b_hh,   // [4H]
                       const float* __restrict__ W_out,  // [1,H]
                       const float* __restrict__ b_out,  // [1]
                       float* __restrict__ out)          // [B,1]
{
    extern __shared__ float smem[];
    float* Wsh  = smem;                  // [KDIM][128]  Wsh[k][j*4+q]
    float* zsh0 = Wsh + KDIM*128;        // [KC][ZS] ping
    float* zsh1 = zsh0 + KC*ZS;          // [KC][ZS] pong
    float* bsh  = zsh1 + KC*ZS;          // [128]    b_ih+b_hh, ordered [j*4+q]

    const int bid = blockIdx.x;
    const int bx  = bid & (NBX - 1);   // batch group
    const int uy  = bid >> 4;          // unit block within group
    const int tid = threadIdx.x;
    const int tb  = tid >> 5;          // warp id -> 4 batch rows (tb*4..tb*4+3)
    const int tr  = tid & 31;          // lane    -> local hidden unit

    volatile unsigned int* genp   = &g_bar_gen[bx];
    unsigned int*          countp = &g_bar_count[bx];
    unsigned int gen_obs = 0;          // only meaningful on tid==0

    // staging thread mapping: 512 threads = 512 float4 units = one chunk
    const int sb  = tid >> 3;            // local batch row 0..63
    const int skg = (tid & 7) * 4;       // k offset within chunk: 0,4,...,28

    // ---- one-time: W slice -> SMEM (gate rows interleaved [unit][gate]) ----
    for (int idx = tid; idx < KDIM * 128; idx += NTHREADS) {
        int k   = idx >> 7;
        int col = idx & 127;
        int j   = col >> 2;
        int q   = col & 3;
        int row = q * HDIM + uy * UN + j;
        Wsh[idx] = (k < IDIM) ? W_ih[row * IDIM + k]
                              : W_hh[row * HDIM + (k - IDIM)];
    }
    if (tid < 128) {
        int j = tid >> 2, q = tid & 3;
        int row = q * HDIM + uy * UN + j;
        bsh[tid] = b_ih[row] + b_hh[row];
    }

    // ---- zero owned h0 slice (buffer 0 is read at t=0) ----
    for (int i = tid; i < BM * UN; i += NTHREADS) {
        int b = i >> 5;
        int j = i & 31;
        __stcg(&g_hbuf[0][(bx * BM + b) * HDIM + uy * UN + j], 0.0f);
    }

    float c[4];
#pragma unroll
    for (int m = 0; m < 4; ++m) c[m] = 0.0f;

    // ---- split group barrier: ARRIVE now; WAIT overlapped into step 0 ----
    __syncthreads();
    __threadfence();
    if (tid == 0) {
        gen_obs = *genp;
        if (atomicAdd(countp, 1u) == NUY - 1) {
            *countp = 0;
            __threadfence();
            atomicAdd(&g_bar_gen[bx], 1u);
        }
    }

    float4 bias4 = *reinterpret_cast<const float4*>(&bsh[tr * 4]);

    // stage an x chunk (ci in {0,1}) of timestep tt into zbuf (1 float4/thread)
    auto stage_x = [&](int ci, float* zbuf, int tt) {
        const int k0 = ci * KC;
        float4 v = __ldg(reinterpret_cast<const float4*>(
            &x[((bx * BM + sb) * TDIM + tt) * IDIM + k0 + skg]));
        zbuf[(skg + 0) * ZS + sb] = v.x;
        zbuf[(skg + 1) * ZS + sb] = v.y;
        zbuf[(skg + 2) * ZS + sb] = v.z;
        zbuf[(skg + 3) * ZS + sb] = v.w;
    };

    // prologue: chunk 0 of t=0
    stage_x(0, zsh0, 0);
    __syncthreads();

#pragma unroll 1
    for (int t = 0; t < TDIM; ++t) {
        const float* hr = g_hbuf[t & 1];
        float*       hw = g_hbuf[(t + 1) & 1];

        // stage an h chunk (ci in 2..9) into zbuf
        auto stage_h = [&](int ci, float* zbuf) {
            const int k0 = ci * KC - IDIM;
            float4 v = __ldcg(reinterpret_cast<const float4*>(
                &hr[(bx * BM + sb) * HDIM + k0 + skg]));
            zbuf[(skg + 0) * ZS + sb] = v.x;
            zbuf[(skg + 1) * ZS + sb] = v.y;
            zbuf[(skg + 2) * ZS + sb] = v.z;
            zbuf[(skg + 3) * ZS + sb] = v.w;
        };

        unsigned long long acc2[4][2];   // [gate q][batch pair p]
#pragma unroll
        for (int q = 0; q < 4; ++q)
#pragma unroll
            for (int p = 0; p < 2; ++p) acc2[q][p] = 0ull;

        // rank-KC FMA2 update from staged zbuf
        auto compute = [&](int ci, const float* zbuf) {
            const int k0 = ci * KC;
#pragma unroll 4
            for (int kk = 0; kk < KC; ++kk) {
                float4 w4 = *reinterpret_cast<const float4*>(
                    &Wsh[(k0 + kk) * 128 + tr * 4]);
                unsigned long long w2[4];
                w2[0] = dup2(w4.x); w2[1] = dup2(w4.y);
                w2[2] = dup2(w4.z); w2[3] = dup2(w4.w);
                ulonglong2 za = *reinterpret_cast<const ulonglong2*>(
                    &zbuf[kk * ZS + tb * 4]);          // batch pairs (0,1),(2,3)
                unsigned long long z2[2] = { za.x, za.y };
#pragma unroll
                for (int q = 0; q < 4; ++q) {
#pragma unroll
                    for (int p = 0; p < 2; ++p) fma2(acc2[q][p], w2[q], z2[p]);
                }
            }
        };

        // --- pipelined chunk schedule (one sync per chunk, LDG hidden) ---
        stage_x(1, zsh1, t);              // load chunk 1 while computing 0
        compute(0, zsh0);
        __syncthreads();

        // WAIT: previous step's h stores from this group visible (overlapped
        // with the x-chunk compute above).
        if (tid == 0) {
            while (*genp == gen_obs) { }
            __threadfence();   // acquire-side ordering before h reads
        }
        __syncthreads();

        stage_h(2, zsh0);                 // first h chunk
        compute(1, zsh1);
        __syncthreads();

#pragma unroll 1
        for (int ci = 2; ci < NCHUNK - 1; ++ci) {
            if ((ci + 1) & 1) stage_h(ci + 1, zsh1);
            else              stage_h(ci + 1, zsh0);
            if (ci & 1) compute(ci, zsh1);
            else        compute(ci, zsh0);
            __syncthreads();
        }

        // prefetch chunk 0 of next step (x-only) under the last compute+epilogue
        if (t + 1 < TDIM) stage_x(0, zsh0, t + 1);
        compute(NCHUNK - 1, zsh1);        // chunk 9 lives in pong buffer

        // ---- epilogue: gates -> (c,h); c stays in registers ----
#pragma unroll
        for (int p = 0; p < 2; ++p) {
            float gi0, gi1, gf0, gf1, gg0, gg1, go0, go1;
            unpack2(acc2[0][p], gi0, gi1);
            unpack2(acc2[1][p], gf0, gf1);
            unpack2(acc2[2][p], gg0, gg1);
            unpack2(acc2[3][p], go0, go1);
#pragma unroll
            for (int h2 = 0; h2 < 2; ++h2) {
                int m = p * 2 + h2;
                float gi = (h2 ? gi1 : gi0) + bias4.x;
                float gf = (h2 ? gf1 : gf0) + bias4.y;
                float gg = (h2 ? gg1 : gg0) + bias4.z;
                float go = (h2 ? go1 : go0) + bias4.w;
                float iv = sigmoidf_(gi);
                float fv = sigmoidf_(gf);
                float gv = tanhf_(gg);
                float ov = sigmoidf_(go);
                float cn = fv * c[m] + iv * gv;
                c[m] = cn;
                float hn = ov * tanhf_(cn);
                __stcg(&hw[(bx * BM + tb * 4 + m) * HDIM + uy * UN + tr], hn);
            }
        }

        // ---- ARRIVE for this step (wait is overlapped into next step).
        // The __syncthreads also orders this step's zsh0 prefetch stores
        // before next step's compute(0) reads. ----
        __syncthreads();
        __threadfence();
        if (tid == 0) {
            gen_obs = *genp;
            if (atomicAdd(countp, 1u) == NUY - 1) {
                *countp = 0;
                __threadfence();
                atomicAdd(&g_bar_gen[bx], 1u);
            }
        }
    }

    // ---- final wait: group's last h stores visible before the head GEMV ----
    if (tid == 0) {
        while (*genp == gen_obs) { }
        __threadfence();
    }
    __syncthreads();

    // ---- output head: out[b] = h_last . W_out + b_out (vectorized) ----
    if (uy == 0 && tid < BM) {
        const float* hl = g_hbuf[TDIM & 1];   // buffer written at t = T-1
        int b = bx * BM + tid;
        float sum = 0.0f;
#pragma unroll 8
        for (int j = 0; j < HDIM; j += 4) {
            float4 hv = *reinterpret_cast<const float4*>(&hl[b * HDIM + j]);
            float4 wv = __ldg(reinterpret_cast<const float4*>(&W_out[j]));
            sum += hv.x * wv.x + hv.y * wv.y + hv.z * wv.z + hv.w * wv.w;
        }
        out[b] = sum + __ldg(&b_out[0]);
    }
}

extern "C" void kernel_launch(void* const* d_in, const int* in_sizes, int n_in,
                              void* d_out, int out_size) {
    const float* input_seq = (const float*)d_in[0];
    const float* W_ih      = (const float*)d_in[1];
    const float* W_hh      = (const float*)d_in[2];
    const float* b_ih      = (const float*)d_in[3];
    const float* b_hh      = (const float*)d_in[4];
    const float* W_out     = (const float*)d_in[5];
    const float* b_out     = (const float*)d_in[6];
    float* out             = (float*)d_out;

    cudaFuncSetAttribute(lstm_persistent_kernel,
                         cudaFuncAttributeMaxDynamicSharedMemorySize, SMEM_BYTES);
    lstm_persistent_kernel<<<GRID_CTAS, NTHREADS, SMEM_BYTES>>>(
        input_seq, W_ih, W_hh, b_ih, b_hh, W_out, b_out, out);
}

// round 13
// speedup vs baseline: 1.9150x; 1.8702x over previous
#include <cuda_runtime.h>
#include <cuda_bf16.h>
#include <cstdint>

// ---------------- problem dims ----------------
#define BDIM 1024
#define TDIM 512
#define IDIM 64
#define HDIM 256
#define KDIM 320
#define NCH  20              // K chunks of 16

// ---------------- partitioning ----------------
#define NBX 16               // batch groups (independent barrier domains)
#define NUY 8                // unit tiles per group
#define GRID_CTAS (NBX*NUY)  // 128 CTAs co-resident
#define BN 64                // batch (GEMM N) per CTA
#define UN 32                // units per CTA -> M = 128 gate rows [unit][gate]
#define NTHREADS 256         // 8 warps; warps 0..3 run mma (one per SMSP)

// ---------------- smem layout (bytes) ----------------
// W rows m=0..127 (m = unit*4 + gate), stride 656B (328 bf16): 4-bank row
// stagger -> conflict-free ldmatrix. z tile [64 n][320 k] bf16, same stride.
#define WSTR 656
#define ZSTR 656
#define WHI_OFF 0
#define WLO_OFF (128*WSTR)           // 83,968
#define Z_OFF   (256*WSTR)           // 167,936 (z; reused as fp32 Dsh)
#define DSTR 132                     // Dsh stride in floats
#define BIAS_OFF (Z_OFF + 64*ZSTR)   // 209,920
#define SMEM_BYTES (BIAS_OFF + 640)  // 210,560 < 232,448

// persistent global state (no allocations allowed)
__device__ __nv_bfloat16 g_xhi[(size_t)TDIM*BDIM*IDIM];   // [t][b][k] planes
__device__ __nv_bfloat16 g_xlo[(size_t)TDIM*BDIM*IDIM];
__device__ __nv_bfloat16 g_hhi[2][BDIM*HDIM];
__device__ __nv_bfloat16 g_hlo[2][BDIM*HDIM];
__device__ unsigned int g_bar_count[NBX];
__device__ unsigned int g_bar_gen[NBX];

static __device__ __forceinline__ uint32_t smem_u32(const void* p) {
    uint32_t a;
    asm("{ .reg .u64 t; cvta.to.shared.u64 t, %1; cvt.u32.u64 %0, t; }" : "=r"(a) : "l"(p));
    return a;
}

#define LDSM4(r, a) asm volatile( \
    "ldmatrix.sync.aligned.m8n8.x4.shared.b16 {%0,%1,%2,%3}, [%4];" \
    : "=r"((r)[0]), "=r"((r)[1]), "=r"((r)[2]), "=r"((r)[3]) : "r"(a))

#define MMA_BF16(d, a, b0, b1) asm volatile( \
    "mma.sync.aligned.m16n8k16.row.col.f32.bf16.bf16.f32 " \
    "{%0,%1,%2,%3}, {%4,%5,%6,%7}, {%8,%9}, {%0,%1,%2,%3};" \
    : "+f"((d)[0]), "+f"((d)[1]), "+f"((d)[2]), "+f"((d)[3]) \
    : "r"((a)[0]), "r"((a)[1]), "r"((a)[2]), "r"((a)[3]), "r"(b0), "r"(b1))

static __device__ __forceinline__ void split1(float v, __nv_bfloat16& h, __nv_bfloat16& l) {
    h = __float2bfloat16_rn(v);
    l = __float2bfloat16_rn(v - __bfloat162float(h));
}
static __device__ __forceinline__ uint32_t bf2u(__nv_bfloat16 a, __nv_bfloat16 b) {
    return (uint32_t)__bfloat16_as_ushort(a) | ((uint32_t)__bfloat16_as_ushort(b) << 16);
}
static __device__ __forceinline__ float sigmoidf_(float x) { return 1.0f / (1.0f + __expf(-x)); }
static __device__ __forceinline__ float tanhf_(float x) {
    float e = __expf(-2.0f * fabsf(x));
    return copysignf((1.0f - e) / (1.0f + e), x);
}

__global__ void __launch_bounds__(NTHREADS, 1)
lstm_mma_kernel(const float* __restrict__ x,      // [B,T,I]
                const float* __restrict__ W_ih,   // [4H,I]
                const float* __restrict__ W_hh,   // [4H,H]
                const float* __restrict__ b_ih,
                const float* __restrict__ b_hh,
                const float* __restrict__ W_out,  // [1,H]
                const float* __restrict__ b_out,
                float* __restrict__ out)          // [B,1]
{
    extern __shared__ char smem[];
    float* Dsh = (float*)(smem + Z_OFF);
    float* bsh = (float*)(smem + BIAS_OFF);
    const uint32_t smb = smem_u32(smem);

    const int bid = blockIdx.x;
    const int bx  = bid & (NBX - 1);
    const int uy  = bid >> 4;
    const int tid = threadIdx.x;
    const int wid = tid >> 5;
    const int lid = tid & 31;
    const int bxB = bx * BN;

    volatile unsigned int* genp   = &g_bar_gen[bx];
    unsigned int*          countp = &g_bar_count[bx];
    unsigned int gen_obs = 0;

    // ---- one-time: W hi/lo split -> smem (rows m = unit*4 + gate) ----
    for (int idx = tid; idx < 128 * KDIM; idx += NTHREADS) {
        int m = idx / KDIM, k = idx - m * KDIM;
        int grow = (m & 3) * HDIM + uy * UN + (m >> 2);
        float w = (k < IDIM) ? W_ih[grow * IDIM + k] : W_hh[grow * HDIM + (k - IDIM)];
        __nv_bfloat16 h, l; split1(w, h, l);
        *(__nv_bfloat16*)(smem + WHI_OFF + m * WSTR + k * 2) = h;
        *(__nv_bfloat16*)(smem + WLO_OFF + m * WSTR + k * 2) = l;
    }
    if (tid < 128) {
        int grow = (tid & 3) * HDIM + uy * UN + (tid >> 2);
        bsh[tid] = b_ih[grow] + b_hh[grow];
    }

    // ---- one-time: pre-split x into [t][b][k] bf16 planes (group-split) ----
    for (int i = uy * 65536 + tid; i < (uy + 1) * 65536; i += NTHREADS) {
        int bl = i >> 13;               // 0..63
        int t  = (i >> 4) & 511;
        int k4 = i & 15;
        float4 v = __ldg((const float4*)&x[(((size_t)(bxB + bl)) * TDIM + t) * IDIM + k4 * 4]);
        __nv_bfloat16 h0,l0,h1,l1,h2,l2,h3,l3;
        split1(v.x,h0,l0); split1(v.y,h1,l1); split1(v.z,h2,l2); split1(v.w,h3,l3);
        size_t di = ((size_t)t * BDIM + bxB + bl) * IDIM + k4 * 4;
        *(uint2*)&g_xhi[di] = make_uint2(bf2u(h0,h1), bf2u(h2,h3));
        *(uint2*)&g_xlo[di] = make_uint2(bf2u(l0,l1), bf2u(l2,l3));
    }

    // ---- zero h0 planes (owned slice) ----
    for (int i = tid; i < BN * UN; i += NTHREADS) {
        int b = i >> 5, u = i & 31;
        g_hhi[0][(bxB + b) * HDIM + uy * UN + u] = __ushort_as_bfloat16(0);
        g_hlo[0][(bxB + b) * HDIM + uy * UN + u] = __ushort_as_bfloat16(0);
    }

    float c4[8];
#pragma unroll
    for (int m = 0; m < 8; ++m) c4[m] = 0.0f;

    __syncthreads();
    __threadfence();
    if (tid == 0) {
        gen_obs = *genp;
        if (atomicAdd(countp, 1u) == NUY - 1) {
            *countp = 0; __threadfence(); atomicAdd(&g_bar_gen[bx], 1u);
        }
    }

    const float4 bias4 = *(const float4*)&bsh[(tid & 31) * 4];

    // ldmatrix lane addresses (mma warps 0..3, warp w owns gate rows w*32..+31)
    uint32_t aHi = 0, aLo = 0, bBase = 0;
    if (wid < 4) {
        int ar  = wid * 32 + (lid & 15);
        int acb = (lid >> 4) * 16;
        aHi = smb + WHI_OFF + ar * WSTR + acb;
        aLo = smb + WLO_OFF + ar * WSTR + acb;
        int br  = (lid & 7) + ((lid >> 4) << 3);
        int bcb = ((lid >> 3) & 1) * 16;
        bBase = smb + Z_OFF + br * ZSTR + bcb;
    }

#pragma unroll 1
    for (int t = 0; t < TDIM; ++t) {
        // ---- stage zhi.x (independent of h; overlaps barrier wait) ----
        {
            const uint4* src = (const uint4*)&g_xhi[((size_t)t * BDIM + bxB) * IDIM];
#pragma unroll
            for (int r = 0; r < 2; ++r) {
                int i = tid + r * NTHREADS;
                uint4 v = __ldg(src + i);
                *(uint4*)(smem + Z_OFF + (i >> 3) * ZSTR + (i & 7) * 16) = v;
            }
        }
        // ---- group barrier wait: h_t visible ----
        if (tid == 0) { while (*genp == gen_obs) { } __threadfence(); }
        __syncthreads();
        // ---- stage zhi.h ----
        {
            const uint4* src = (const uint4*)&g_hhi[t & 1][bxB * HDIM];
#pragma unroll
            for (int r = 0; r < 8; ++r) {
                int i = tid + r * NTHREADS;
                uint4 v = __ldcg(src + i);
                *(uint4*)(smem + Z_OFF + (i >> 5) * ZSTR + (8 + (i & 31)) * 16) = v;
            }
        }
        __syncthreads();

        float acc[2][8][4];
#pragma unroll
        for (int a = 0; a < 2; ++a)
#pragma unroll
            for (int b = 0; b < 8; ++b)
#pragma unroll
                for (int c = 0; c < 4; ++c) acc[a][b][c] = 0.0f;

        // ---- passes 1&2: (Whi + Wlo) x zhi ----
        if (wid < 4) {
#pragma unroll 2
            for (int ci = 0; ci < NCH; ++ci) {
                uint32_t ah0[4], ah1[4], al0[4], al1[4], bb[4][4];
                LDSM4(ah0, aHi + ci * 32);
                LDSM4(ah1, aHi + 16 * WSTR + ci * 32);
                LDSM4(al0, aLo + ci * 32);
                LDSM4(al1, aLo + 16 * WSTR + ci * 32);
#pragma unroll
                for (int p = 0; p < 4; ++p) LDSM4(bb[p], bBase + p * 16 * ZSTR + ci * 32);
#pragma unroll
                for (int p = 0; p < 4; ++p) {
                    MMA_BF16(acc[0][2*p],   ah0, bb[p][0], bb[p][1]);
                    MMA_BF16(acc[0][2*p+1], ah0, bb[p][2], bb[p][3]);
                    MMA_BF16(acc[1][2*p],   ah1, bb[p][0], bb[p][1]);
                    MMA_BF16(acc[1][2*p+1], ah1, bb[p][2], bb[p][3]);
                    MMA_BF16(acc[0][2*p],   al0, bb[p][0], bb[p][1]);
                    MMA_BF16(acc[0][2*p+1], al0, bb[p][2], bb[p][3]);
                    MMA_BF16(acc[1][2*p],   al1, bb[p][0], bb[p][1]);
                    MMA_BF16(acc[1][2*p+1], al1, bb[p][2], bb[p][3]);
                }
            }
        }
        __syncthreads();
        // ---- stage zlo ----
        {
            const uint4* srcx = (const uint4*)&g_xlo[((size_t)t * BDIM + bxB) * IDIM];
#pragma unroll
            for (int r = 0; r < 2; ++r) {
                int i = tid + r * NTHREADS;
                uint4 v = __ldg(srcx + i);
                *(uint4*)(smem + Z_OFF + (i >> 3) * ZSTR + (i & 7) * 16) = v;
            }
            const uint4* srch = (const uint4*)&g_hlo[t & 1][bxB * HDIM];
#pragma unroll
            for (int r = 0; r < 8; ++r) {
                int i = tid + r * NTHREADS;
                uint4 v = __ldcg(srch + i);
                *(uint4*)(smem + Z_OFF + (i >> 5) * ZSTR + (8 + (i & 31)) * 16) = v;
            }
        }
        __syncthreads();
        // ---- pass 3: Whi x zlo ----
        if (wid < 4) {
#pragma unroll 2
            for (int ci = 0; ci < NCH; ++ci) {
                uint32_t ah0[4], ah1[4], bb[4][4];
                LDSM4(ah0, aHi + ci * 32);
                LDSM4(ah1, aHi + 16 * WSTR + ci * 32);
#pragma unroll
                for (int p = 0; p < 4; ++p) LDSM4(bb[p], bBase + p * 16 * ZSTR + ci * 32);
#pragma unroll
                for (int p = 0; p < 4; ++p) {
                    MMA_BF16(acc[0][2*p],   ah0, bb[p][0], bb[p][1]);
                    MMA_BF16(acc[0][2*p+1], ah0, bb[p][2], bb[p][3]);
                    MMA_BF16(acc[1][2*p],   ah1, bb[p][0], bb[p][1]);
                    MMA_BF16(acc[1][2*p+1], ah1, bb[p][2], bb[p][3]);
                }
            }
        }
        __syncthreads();                  // zlo fully consumed; z becomes Dsh
        // ---- write acc -> Dsh[batch][gate-row] ----
        if (wid < 4) {
            int gidr = lid >> 2, tig = lid & 3;
#pragma unroll
            for (int m2 = 0; m2 < 2; ++m2)
#pragma unroll
                for (int nt = 0; nt < 8; ++nt) {
                    int m = wid * 32 + m2 * 16 + gidr;
                    int n = nt * 8 + tig * 2;
                    Dsh[n * DSTR + m]           = acc[m2][nt][0];
                    Dsh[(n + 1) * DSTR + m]     = acc[m2][nt][1];
                    Dsh[n * DSTR + m + 8]       = acc[m2][nt][2];
                    Dsh[(n + 1) * DSTR + m + 8] = acc[m2][nt][3];
                }
        }
        __syncthreads();
        // ---- epilogue: gates -> (c,h); h stored as bf16 hi/lo planes ----
        {
            __nv_bfloat16* hhw = g_hhi[(t + 1) & 1];
            __nv_bfloat16* hlw = g_hlo[(t + 1) & 1];
            int u = tid & 31;
#pragma unroll
            for (int p = 0; p < 8; ++p) {
                int b = (tid >> 5) * 8 + p;
                float4 g4 = *(const float4*)&Dsh[b * DSTR + u * 4];
                float gi = g4.x + bias4.x;
                float gf = g4.y + bias4.y;
                float gg = g4.z + bias4.z;
                float go = g4.w + bias4.w;
                float cn = sigmoidf_(gf) * c4[p] + sigmoidf_(gi) * tanhf_(gg);
                c4[p] = cn;
                float hn = sigmoidf_(go) * tanhf_(cn);
                __nv_bfloat16 hh, hl; split1(hn, hh, hl);
                hhw[(bxB + b) * HDIM + uy * UN + u] = hh;
                hlw[(bxB + b) * HDIM + uy * UN + u] = hl;
            }
        }
        __threadfence();
        __syncthreads();
        if (tid == 0) {
            gen_obs = *genp;
            if (atomicAdd(countp, 1u) == NUY - 1) {
                *countp = 0; __threadfence(); atomicAdd(&g_bar_gen[bx], 1u);
            }
        }
    }

    // ---- final wait + output head ----
    if (tid == 0) { while (*genp == gen_obs) { } __threadfence(); }
    __syncthreads();

    if (uy == 0 && tid < BN) {
        int b = bxB + tid;
        float sum = 0.0f;
#pragma unroll 8
        for (int j = 0; j < HDIM; ++j) {
            float hv = __bfloat162float(g_hhi[0][b * HDIM + j])
                     + __bfloat162float(g_hlo[0][b * HDIM + j]);
            sum += hv * __ldg(&W_out[j]);
        }
        out[b] = sum + __ldg(&b_out[0]);
    }
}

extern "C" void kernel_launch(void* const* d_in, const int* in_sizes, int n_in,
                              void* d_out, int out_size) {
    const float* input_seq = (const float*)d_in[0];
    const float* W_ih      = (const float*)d_in[1];
    const float* W_hh      = (const float*)d_in[2];
    const float* b_ih      = (const float*)d_in[3];
    const float* b_hh      = (const float*)d_in[4];
    const float* W_out     = (const float*)d_in[5];
    const float* b_out     = (const float*)d_in[6];
    float* out             = (float*)d_out;

    cudaFuncSetAttribute(lstm_mma_kernel,
                         cudaFuncAttributeMaxDynamicSharedMemorySize, SMEM_BYTES);
    lstm_mma_kernel<<<GRID_CTAS, NTHREADS, SMEM_BYTES>>>(
        input_seq, W_ih, W_hh, b_ih, b_hh, W_out, b_out, out);
}

// round 14
// speedup vs baseline: 2.1853x; 1.1411x over previous
#include <cuda_runtime.h>
#include <cuda_bf16.h>
#include <cstdint>

// ---------------- problem dims ----------------
#define BDIM 1024
#define TDIM 512
#define IDIM 64
#define HDIM 256
#define KDIM 320

// ---------------- partitioning ----------------
#define NBX 16               // batch groups (independent barrier domains)
#define NUY 8                // unit tiles per group
#define GRID_CTAS (NBX*NUY)  // 128 CTAs co-resident
#define BN 64                // batch (GEMM N) per CTA
#define UN 32                // units per CTA -> M = 128 gate rows [unit][gate]
#define NTHREADS 256         // warps 0..3 mma (1/SMSP), warps 4..7 stagers

// ---------------- smem layout (bytes) ----------------
#define WSTR 656                     // 320 bf16 + pad -> conflict-free ldmatrix
#define ZSTR 336                     // 160 bf16 + pad -> conflict-free ldmatrix
#define WHI_OFF 0
#define WLO_OFF (128*WSTR)           // 83,968
#define ZA_OFF  (256*WSTR)           // 167,936  z half A (K 0..159)
#define ZB_OFF  (ZA_OFF + 64*ZSTR)   // 189,440  z half B (K 160..319)
#define DSTR 132                     // fp32 Dsh stride (reuses zA/zB region)
#define BIAS_OFF (ZB_OFF + 64*ZSTR)  // 210,944
#define SMEM_BYTES (BIAS_OFF + 640)  // 211,584 < 232,448

// persistent global state (no allocations allowed)
__device__ __nv_bfloat16 g_xhi[(size_t)TDIM*BDIM*IDIM];   // [t][b][k] planes
__device__ __nv_bfloat16 g_xlo[(size_t)TDIM*BDIM*IDIM];
__device__ __nv_bfloat16 g_hhi[2][BDIM*HDIM];
__device__ __nv_bfloat16 g_hlo[2][BDIM*HDIM];
__device__ unsigned int g_bar_count[NBX];
__device__ unsigned int g_bar_gen[NBX];

static __device__ __forceinline__ uint32_t smem_u32(const void* p) {
    uint32_t a;
    asm("{ .reg .u64 t; cvta.to.shared.u64 t, %1; cvt.u32.u64 %0, t; }" : "=r"(a) : "l"(p));
    return a;
}

#define LDSM4(r, a) asm volatile( \
    "ldmatrix.sync.aligned.m8n8.x4.shared.b16 {%0,%1,%2,%3}, [%4];" \
    : "=r"((r)[0]), "=r"((r)[1]), "=r"((r)[2]), "=r"((r)[3]) : "r"(a))

#define MMA_BF16(d, a, b0, b1) asm volatile( \
    "mma.sync.aligned.m16n8k16.row.col.f32.bf16.bf16.f32 " \
    "{%0,%1,%2,%3}, {%4,%5,%6,%7}, {%8,%9}, {%0,%1,%2,%3};" \
    : "+f"((d)[0]), "+f"((d)[1]), "+f"((d)[2]), "+f"((d)[3]) \
    : "r"((a)[0]), "r"((a)[1]), "r"((a)[2]), "r"((a)[3]), "r"(b0), "r"(b1))

static __device__ __forceinline__ void split1(float v, __nv_bfloat16& h, __nv_bfloat16& l) {
    h = __float2bfloat16_rn(v);
    l = __float2bfloat16_rn(v - __bfloat162float(h));
}
static __device__ __forceinline__ uint32_t bf2u(__nv_bfloat16 a, __nv_bfloat16 b) {
    return (uint32_t)__bfloat16_as_ushort(a) | ((uint32_t)__bfloat16_as_ushort(b) << 16);
}
static __device__ __forceinline__ float sigmoidf_(float x) { return 1.0f / (1.0f + __expf(-x)); }
static __device__ __forceinline__ float tanhf_(float x) {
    float e = __expf(-2.0f * fabsf(x));
    return copysignf((1.0f - e) / (1.0f + e), x);
}

__global__ void __launch_bounds__(NTHREADS, 1)
lstm_mma_kernel(const float* __restrict__ x,      // [B,T,I]
                const float* __restrict__ W_ih,   // [4H,I]
                const float* __restrict__ W_hh,   // [4H,H]
                const float* __restrict__ b_ih,
                const float* __restrict__ b_hh,
                const float* __restrict__ W_out,  // [1,H]
                const float* __restrict__ b_out,
                float* __restrict__ out)          // [B,1]
{
    extern __shared__ char smem[];
    float* Dsh = (float*)(smem + ZA_OFF);
    float* bsh = (float*)(smem + BIAS_OFF);
    const uint32_t smb = smem_u32(smem);

    const int bid = blockIdx.x;
    const int bx  = bid & (NBX - 1);
    const int uy  = bid >> 4;
    const int tid = threadIdx.x;
    const int wid = tid >> 5;
    const int lid = tid & 31;
    const int bxB = bx * BN;

    volatile unsigned int* genp   = &g_bar_gen[bx];
    unsigned int*          countp = &g_bar_count[bx];
    unsigned int gen_obs = 0;

    // ---- one-time: W hi/lo split -> smem (rows m = unit*4 + gate) ----
    for (int idx = tid; idx < 128 * KDIM; idx += NTHREADS) {
        int m = idx / KDIM, k = idx - m * KDIM;
        int grow = (m & 3) * HDIM + uy * UN + (m >> 2);
        float w = (k < IDIM) ? W_ih[grow * IDIM + k] : W_hh[grow * HDIM + (k - IDIM)];
        __nv_bfloat16 h, l; split1(w, h, l);
        *(__nv_bfloat16*)(smem + WHI_OFF + m * WSTR + k * 2) = h;
        *(__nv_bfloat16*)(smem + WLO_OFF + m * WSTR + k * 2) = l;
    }
    if (tid < 128) {
        int grow = (tid & 3) * HDIM + uy * UN + (tid >> 2);
        bsh[tid] = b_ih[grow] + b_hh[grow];
    }

    // ---- one-time: pre-split x into [t][b][k] bf16 planes (group-split) ----
    for (int i = uy * 65536 + tid; i < (uy + 1) * 65536; i += NTHREADS) {
        int bl = i >> 13;
        int t  = (i >> 4) & 511;
        int k4 = i & 15;
        float4 v = __ldg((const float4*)&x[(((size_t)(bxB + bl)) * TDIM + t) * IDIM + k4 * 4]);
        __nv_bfloat16 h0,l0,h1,l1,h2,l2,h3,l3;
        split1(v.x,h0,l0); split1(v.y,h1,l1); split1(v.z,h2,l2); split1(v.w,h3,l3);
        size_t di = ((size_t)t * BDIM + bxB + bl) * IDIM + k4 * 4;
        *(uint2*)&g_xhi[di] = make_uint2(bf2u(h0,h1), bf2u(h2,h3));
        *(uint2*)&g_xlo[di] = make_uint2(bf2u(l0,l1), bf2u(l2,l3));
    }

    // ---- zero h0 planes (owned slice) ----
    for (int i = tid; i < BN * UN; i += NTHREADS) {
        int b = i >> 5, u = i & 31;
        g_hhi[0][(bxB + b) * HDIM + uy * UN + u] = __ushort_as_bfloat16(0);
        g_hlo[0][(bxB + b) * HDIM + uy * UN + u] = __ushort_as_bfloat16(0);
    }

    float c4[8];
#pragma unroll
    for (int m = 0; m < 8; ++m) c4[m] = 0.0f;

    // ---- prologue barrier: arrive AND wait (x presplit + h0 visible
    //      group-wide before any staging; fixes round-13 t=0 race) ----
    __syncthreads();
    __threadfence();
    if (tid == 0) {
        unsigned int g0 = *genp;
        if (atomicAdd(countp, 1u) == NUY - 1) {
            *countp = 0; __threadfence(); atomicAdd(&g_bar_gen[bx], 1u);
        }
        while (*genp == g0) { }
        __threadfence();
    }
    __syncthreads();

    const float4 bias4 = *(const float4*)&bsh[(tid & 31) * 4];

    // ldmatrix lane addresses
    uint32_t aHi = 0, aLo = 0, bLane = 0;
    {
        int ar  = (wid & 3) * 32 + (lid & 15);
        int acb = (lid >> 4) * 16;
        aHi = smb + WHI_OFF + ar * WSTR + acb;
        aLo = smb + WLO_OFF + ar * WSTR + acb;
        int br  = (lid & 7) + ((lid >> 4) << 3);
        int bcb = ((lid >> 3) & 1) * 16;
        bLane = br * ZSTR + bcb;
    }
    const uint32_t zbA = smb + ZA_OFF + bLane;
    const uint32_t zbB = smb + ZB_OFF + bLane;
    const int s = tid & 127;   // stager index (warps 4..7)

#pragma unroll 1
    for (int t = 0; t < TDIM; ++t) {
        const __nv_bfloat16* hhi = g_hhi[t & 1];
        const __nv_bfloat16* hlo = g_hlo[t & 1];

        // stage x (K 0..63) of plane into zA rows [*][0..127]
        auto stage_xA = [&](const __nv_bfloat16* xp) {
#pragma unroll
            for (int r = 0; r < 4; ++r) {
                int i = s + r * 128;
                int row = i >> 3, c = i & 7;
                uint4 v = __ldg((const uint4*)&xp[((size_t)t * BDIM + bxB + row) * IDIM + c * 8]);
                *(uint4*)(smem + ZA_OFF + row * ZSTR + c * 16) = v;
            }
        };
        // stage h k 0..95 into zA rows [*][128..319]; nthr threads, idx base
        auto stage_hA_all = [&](const __nv_bfloat16* hp) {   // 256 thr, 3 ea
#pragma unroll
            for (int r = 0; r < 3; ++r) {
                int i = tid + r * 256;
                int row = i / 12, c = i - row * 12;
                uint4 v = __ldcg((const uint4*)&hp[(bxB + row) * HDIM + c * 8]);
                *(uint4*)(smem + ZA_OFF + row * ZSTR + 128 + c * 16) = v;
            }
        };
        auto stage_hA_half = [&](const __nv_bfloat16* hp) {  // 128 stagers, 6 ea
#pragma unroll
            for (int r = 0; r < 6; ++r) {
                int i = s + r * 128;
                int row = i / 12, c = i - row * 12;
                uint4 v = __ldcg((const uint4*)&hp[(bxB + row) * HDIM + c * 8]);
                *(uint4*)(smem + ZA_OFF + row * ZSTR + 128 + c * 16) = v;
            }
        };
        // stage h k 96..255 into zB rows [*][0..319]; 128 stagers, 10 ea
        auto stage_zB = [&](const __nv_bfloat16* hp) {
#pragma unroll
            for (int r = 0; r < 10; ++r) {
                int i = s + r * 128;
                int row = i / 20, c = i - row * 20;
                uint4 v = __ldcg((const uint4*)&hp[(bxB + row) * HDIM + 96 + c * 8]);
                *(uint4*)(smem + ZB_OFF + row * ZSTR + c * 16) = v;
            }
        };

        float acc[2][8][4];
#pragma unroll
        for (int a = 0; a < 2; ++a)
#pragma unroll
            for (int b = 0; b < 8; ++b)
#pragma unroll
                for (int c = 0; c < 4; ++c) acc[a][b][c] = 0.0f;

        // pass12: (Whi + Wlo) x zhalf, 10 chunks, fragment-pipelined
        auto pass12 = [&](uint32_t zb, int c0) {
            uint32_t fa0[2][4], fa1[2][4], fl0[2][4], fl1[2][4], fb[2][4][4];
            auto ld = [&](int sbuf, int j) {
                int ci = c0 + j;
                LDSM4(fa0[sbuf], aHi + ci * 32);
                LDSM4(fa1[sbuf], aHi + 16 * WSTR + ci * 32);
                LDSM4(fl0[sbuf], aLo + ci * 32);
                LDSM4(fl1[sbuf], aLo + 16 * WSTR + ci * 32);
#pragma unroll
                for (int p = 0; p < 4; ++p) LDSM4(fb[sbuf][p], zb + p * 16 * ZSTR + j * 32);
            };
            ld(0, 0);
#pragma unroll
            for (int j = 0; j < 10; ++j) {
                int sb = j & 1;
                if (j < 9) ld(sb ^ 1, j + 1);
#pragma unroll
                for (int p = 0; p < 4; ++p) {
                    MMA_BF16(acc[0][2*p],   fa0[sb], fb[sb][p][0], fb[sb][p][1]);
                    MMA_BF16(acc[0][2*p+1], fa0[sb], fb[sb][p][2], fb[sb][p][3]);
                    MMA_BF16(acc[1][2*p],   fa1[sb], fb[sb][p][0], fb[sb][p][1]);
                    MMA_BF16(acc[1][2*p+1], fa1[sb], fb[sb][p][2], fb[sb][p][3]);
                    MMA_BF16(acc[0][2*p],   fl0[sb], fb[sb][p][0], fb[sb][p][1]);
                    MMA_BF16(acc[0][2*p+1], fl0[sb], fb[sb][p][2], fb[sb][p][3]);
                    MMA_BF16(acc[1][2*p],   fl1[sb], fb[sb][p][0], fb[sb][p][1]);
                    MMA_BF16(acc[1][2*p+1], fl1[sb], fb[sb][p][2], fb[sb][p][3]);
                }
            }
        };
        // pass3: Whi x zlo-half
        auto pass3 = [&](uint32_t zb, int c0) {
            uint32_t fa0[2][4], fa1[2][4], fb[2][4][4];
            auto ld = [&](int sbuf, int j) {
                int ci = c0 + j;
                LDSM4(fa0[sbuf], aHi + ci * 32);
                LDSM4(fa1[sbuf], aHi + 16 * WSTR + ci * 32);
#pragma unroll
                for (int p = 0; p < 4; ++p) LDSM4(fb[sbuf][p], zb + p * 16 * ZSTR + j * 32);
            };
            ld(0, 0);
#pragma unroll
            for (int j = 0; j < 10; ++j) {
                int sb = j & 1;
                if (j < 9) ld(sb ^ 1, j + 1);
#pragma unroll
                for (int p = 0; p < 4; ++p) {
                    MMA_BF16(acc[0][2*p],   fa0[sb], fb[sb][p][0], fb[sb][p][1]);
                    MMA_BF16(acc[0][2*p+1], fa0[sb], fb[sb][p][2], fb[sb][p][3]);
                    MMA_BF16(acc[1][2*p],   fa1[sb], fb[sb][p][0], fb[sb][p][1]);
                    MMA_BF16(acc[1][2*p+1], fa1[sb], fb[sb][p][2], fb[sb][p][3]);
                }
            }
        };

        // ---- schedule ----
        if (wid >= 4) stage_xA(g_xhi);                       // overlaps wait
        if (t > 0 && tid == 0) { while (*genp == gen_obs) { } __threadfence(); }
        __syncthreads();                                     // S1: h_t visible
        stage_hA_all(hhi);                                   // all threads
        __syncthreads();                                     // S2
        if (wid < 4) pass12(zbA, 0);  else stage_zB(hhi);    // C1 || zB-hi
        __syncthreads();                                     // S3
        if (wid < 4) pass12(zbB, 10);
        else { stage_xA(g_xlo); stage_hA_half(hlo); }        // C2 || zA-lo
        __syncthreads();                                     // S4
        if (wid < 4) pass3(zbA, 0);   else stage_zB(hlo);    // C3 || zB-lo
        __syncthreads();                                     // S5
        if (wid < 4) pass3(zbB, 10);                         // C4
        __syncthreads();                                     // S6: z free -> Dsh
        if (wid < 4) {
            int gidr = lid >> 2, tig = lid & 3;
#pragma unroll
            for (int m2 = 0; m2 < 2; ++m2)
#pragma unroll
                for (int nt = 0; nt < 8; ++nt) {
                    int m = wid * 32 + m2 * 16 + gidr;
                    int n = nt * 8 + tig * 2;
                    Dsh[n * DSTR + m]           = acc[m2][nt][0];
                    Dsh[(n + 1) * DSTR + m]     = acc[m2][nt][1];
                    Dsh[n * DSTR + m + 8]       = acc[m2][nt][2];
                    Dsh[(n + 1) * DSTR + m + 8] = acc[m2][nt][3];
                }
        }
        __syncthreads();                                     // S7
        {
            __nv_bfloat16* hhw = g_hhi[(t + 1) & 1];
            __nv_bfloat16* hlw = g_hlo[(t + 1) & 1];
            int u = tid & 31;
#pragma unroll
            for (int p = 0; p < 8; ++p) {
                int b = (tid >> 5) * 8 + p;
                float4 g4 = *(const float4*)&Dsh[b * DSTR + u * 4];
                float gi = g4.x + bias4.x;
                float gf = g4.y + bias4.y;
                float gg = g4.z + bias4.z;
                float go = g4.w + bias4.w;
                float cn = sigmoidf_(gf) * c4[p] + sigmoidf_(gi) * tanhf_(gg);
                c4[p] = cn;
                float hn = sigmoidf_(go) * tanhf_(cn);
                __nv_bfloat16 hh, hl; split1(hn, hh, hl);
                hhw[(bxB + b) * HDIM + uy * UN + u] = hh;
                hlw[(bxB + b) * HDIM + uy * UN + u] = hl;
            }
        }
        __threadfence();
        __syncthreads();                                     // S8
        if (tid == 0) {
            gen_obs = *genp;
            if (atomicAdd(countp, 1u) == NUY - 1) {
                *countp = 0; __threadfence(); atomicAdd(&g_bar_gen[bx], 1u);
            }
        }
    }

    // ---- final wait + output head ----
    if (tid == 0) { while (*genp == gen_obs) { } __threadfence(); }
    __syncthreads();

    if (uy == 0 && tid < BN) {
        int b = bxB + tid;
        float sum = 0.0f;
#pragma unroll 8
        for (int j = 0; j < HDIM; ++j) {
            float hv = __bfloat162float(g_hhi[0][b * HDIM + j])
                     + __bfloat162float(g_hlo[0][b * HDIM + j]);
            sum += hv * __ldg(&W_out[j]);
        }
        out[b] = sum + __ldg(&b_out[0]);
    }
}

extern "C" void kernel_launch(void* const* d_in, const int* in_sizes, int n_in,
                              void* d_out, int out_size) {
    const float* input_seq = (const float*)d_in[0];
    const float* W_ih      = (const float*)d_in[1];
    const float* W_hh      = (const float*)d_in[2];
    const float* b_ih      = (const float*)d_in[3];
    const float* b_hh      = (const float*)d_in[4];
    const float* W_out     = (const float*)d_in[5];
    const float* b_out     = (const float*)d_in[6];
    float* out             = (float*)d_out;

    cudaFuncSetAttribute(lstm_mma_kernel,
                         cudaFuncAttributeMaxDynamicSharedMemorySize, SMEM_BYTES);
    lstm_mma_kernel<<<GRID_CTAS, NTHREADS, SMEM_BYTES>>>(
        input_seq, W_ih, W_hh, b_ih, b_hh, W_out, b_out, out);
}